// round 14
// baseline (speedup 1.0000x reference)
#include <cuda_runtime.h>
#include <cuda_fp16.h>
#include <cstdint>
#include <math_constants.h>

#define ENC_DIM 512
#define DEC_DIM 1024
#define HID     128
#define BB      64
#define TT      2048

// ---------------- scratch (no cudaMalloc allowed) ----------------
__device__ float  g_q[BB * HID];
__device__ float  g_p[BB * TT];              // unnormalized exp(s - m_local)
__device__ float  g_ctx_part[16][BB][ENC_DIM];
__device__ float  g_stats[BB][16][2];        // per-tile {m_local, sum_local}
__device__ int    g_mask_u8;                 // static-init 0; idempotent 0->1
__device__ int    g_cnt[BB];                 // last-CTA counters (self-resetting)
__device__ __half g_Vw_h[HID * ENC_DIM];

// ---------------- helpers ----------------
__device__ __forceinline__ uint32_t smem_u32(const void* p) {
    uint32_t a;
    asm("{ .reg .u64 t; cvta.to.shared.u64 t, %1; cvt.u32.u64 %0, t; }" : "=r"(a) : "l"(p));
    return a;
}
__device__ __forceinline__ void cp_async16(uint32_t dst, const void* src) {
    asm volatile("cp.async.cg.shared.global [%0], [%1], 16;" :: "r"(dst), "l"(src));
}
#define CP_COMMIT()  asm volatile("cp.async.commit_group;" ::: "memory")
#define CP_WAIT(n)   asm volatile("cp.async.wait_group %0;" :: "n"(n) : "memory")

#define LDSM_X4(r0, r1, r2, r3, addr)                                        \
    asm volatile("ldmatrix.sync.aligned.m8n8.x4.shared.b16 {%0,%1,%2,%3}, [%4];" \
                 : "=r"(r0), "=r"(r1), "=r"(r2), "=r"(r3) : "r"(addr))

__global__ void spacer_kernel() {}

// ---------------- kernel 1: q projection + Vw fp16 conversion + mask detect ----
__global__ void prep_kernel(const float* __restrict__ dec,
                            const float* __restrict__ Ww,
                            const float* __restrict__ Vw,
                            const uint4* __restrict__ mask4) {
    int blk = blockIdx.x;
    int tid = threadIdx.x;     // 256
    if (blk < BB) {
        __shared__ float sdec[DEC_DIM];
        for (int i = tid; i < DEC_DIM; i += 256)
            sdec[i] = dec[blk * DEC_DIM + i];
        __syncthreads();
        if (tid < HID) {
            const float4* wr = (const float4*)(Ww + (size_t)tid * DEC_DIM);
            const float4* dr = (const float4*)sdec;
            float acc = 0.f;
#pragma unroll 8
            for (int i = 0; i < DEC_DIM / 4; i++) {
                float4 w4 = wr[i];
                float4 d4 = dr[i];
                acc += w4.x * d4.x + w4.y * d4.y + w4.z * d4.z + w4.w * d4.w;
            }
            g_q[blk * HID + tid] = acc;
        }
    } else if (blk < BB + 64) {
        int idx = (blk - BB) * 256 + tid;          // 0..16383 float4s
        float4 v = ((const float4*)Vw)[idx];
        __half2 h0 = __floats2half2_rn(v.x, v.y);
        __half2 h1 = __floats2half2_rn(v.z, v.w);
        uint2 u;
        u.x = *(unsigned*)&h0;
        u.y = *(unsigned*)&h1;
        ((uint2*)g_Vw_h)[idx] = u;
    } else {
        // mask dtype detect: 32 blocks x 256 threads = 8192 uint4 words
        int i = (blk - BB - 64) * 256 + tid;
        uint4 v = mask4[i];
        int found = (v.x > 1u) | (v.y > 1u) | (v.z > 1u) | (v.w > 1u);
        found = __any_sync(0xffffffffu, found);
        if ((tid & 31) == 0 && found) atomicOr(&g_mask_u8, 1);
    }
}

// ---------------- kernel 2: fused scores + softmax partials + ctx partial + combine
#define KC        64
#define PITCH     36                      // words/row: 128B data + 16B pad
#define TILE_W    (128 * PITCH)           // 4608 words = 18KB
#define NCHUNK    (ENC_DIM / KC)          // 8
#define A_OFF_W   0
#define B_OFF_W   (2 * TILE_W)
#define DYN_BYTES ((2 + 3) * TILE_W * 4)  // 92160 B

__global__ __launch_bounds__(256, 2) void scores_kernel(
    const float* __restrict__ enc, const unsigned char* __restrict__ mask,
    const float* __restrict__ Vb, const float* __restrict__ ww,
    const float* __restrict__ wb,
    float* __restrict__ out_ctx, float* __restrict__ out_w)
{
    extern __shared__ unsigned dsm[];
    __shared__ float sVb[HID], sq[HID], sw[HID];
    __shared__ float srow[128];
    __shared__ float red[4];
    __shared__ float bc[2];
    __shared__ int   s_last;

    int bidx = blockIdx.x;         // 0..1023
    int b    = bidx >> 4;
    int tile = bidx & 15;
    int t0   = tile << 7;

    int tid    = threadIdx.x;
    int lane   = tid & 31;
    int wid    = tid >> 5;
    int warp_m = wid >> 1;         // 0..3
    int warp_n = wid & 1;          // 0..1
    int g      = lane >> 2;        // 0..7
    int tig    = lane & 3;         // 0..3

    if (tid < HID) {
        sVb[tid]  = Vb[tid];
        sq[tid]   = g_q[b * HID + tid];
        sw[tid]   = ww[tid];
        srow[tid] = 0.f;
    }

    const float*  Ag  = enc + ((size_t)(b * TT + t0)) * ENC_DIM;
    const __half* Bg  = g_Vw_h;
    uint32_t dyn_addr = smem_u32(dsm);

    // ldmatrix lane-address components (PITCH*4 = 144B rows; 9r mod 8 = r -> no conflicts)
    int mat = lane >> 3;
    int ri  = lane & 7;
    uint32_t aRowByte0 = (uint32_t)(warp_m * 32 + (mat & 1) * 8 + ri) * (PITCH * 4)
                       + (uint32_t)(mat >> 1) * 16;
    uint32_t aRowByte1 = aRowByte0 + 16 * (PITCH * 4);
    uint32_t bRowByte[4];
#pragma unroll
    for (int p = 0; p < 4; p++)
        bRowByte[p] = (uint32_t)(warp_n * 64 + p * 16 + (mat >> 1) * 8 + ri) * (PITCH * 4)
                    + (uint32_t)(mat & 1) * 16;

    float4 R[4];   // A prefetch: HALF a chunk (k-half h: 32 floats/row slice)

    auto ldgA = [&](int c, int h) {
#pragma unroll
        for (int i = 0; i < 4; i++) {
            int idx = tid + i * 256;          // 0..1023
            int row = idx >> 3;               // 0..127
            int u   = idx & 7;                // 16B unit within half
            R[i] = *(const float4*)(Ag + (size_t)row * ENC_DIM + c * KC + h * 32 + u * 4);
        }
    };
    auto stsA = [&](int c, int h) {
        unsigned* dst = dsm + A_OFF_W + (c & 1) * TILE_W;
#pragma unroll
        for (int i = 0; i < 4; i++) {
            int idx = tid + i * 256;
            int row = idx >> 3;
            int u   = idx & 7;
            __half2 h0 = __floats2half2_rn(R[i].x, R[i].y);
            __half2 h1 = __floats2half2_rn(R[i].z, R[i].w);
            uint2 v;
            v.x = *(unsigned*)&h0;
            v.y = *(unsigned*)&h1;
            *(uint2*)&dst[row * PITCH + h * 16 + u * 2] = v;
        }
    };
    auto ldB = [&](int c) {
        uint32_t sb = dyn_addr + (B_OFF_W + (c % 3) * TILE_W) * 4;
#pragma unroll
        for (int i = 0; i < 4; i++) {
            int idx = tid + i * 256;          // 0..1023
            int row = idx >> 3;               // 0..127
            int u   = idx & 7;                // 16B unit (8 halves)
            cp_async16(sb + (row * PITCH + u * 4) * 4,
                       Bg + (size_t)row * ENC_DIM + c * KC + u * 8);
        }
        CP_COMMIT();
    };

    float c_[2][8][4];
#pragma unroll
    for (int mt = 0; mt < 2; mt++)
#pragma unroll
        for (int nt = 0; nt < 8; nt++)
#pragma unroll
            for (int r = 0; r < 4; r++) c_[mt][nt][r] = 0.f;

    auto mma_ks = [&](int c, int ks) {
        uint32_t As_b = dyn_addr + (A_OFF_W + (c & 1) * TILE_W) * 4;
        uint32_t Bs_b = dyn_addr + (B_OFF_W + (c % 3) * TILE_W) * 4;
        uint32_t kbyte = ks * 32;
        unsigned a[2][4];
        LDSM_X4(a[0][0], a[0][1], a[0][2], a[0][3], As_b + aRowByte0 + kbyte);
        LDSM_X4(a[1][0], a[1][1], a[1][2], a[1][3], As_b + aRowByte1 + kbyte);
        unsigned bb[4][4];
#pragma unroll
        for (int p = 0; p < 4; p++)
            LDSM_X4(bb[p][0], bb[p][1], bb[p][2], bb[p][3], Bs_b + bRowByte[p] + kbyte);
#pragma unroll
        for (int nt = 0; nt < 8; nt++) {
            unsigned b0 = bb[nt >> 1][(nt & 1) * 2];
            unsigned b1 = bb[nt >> 1][(nt & 1) * 2 + 1];
#pragma unroll
            for (int mt = 0; mt < 2; mt++) {
                asm volatile(
                    "mma.sync.aligned.m16n8k16.row.col.f32.f16.f16.f32 "
                    "{%0,%1,%2,%3}, {%4,%5,%6,%7}, {%8,%9}, {%0,%1,%2,%3};"
                    : "+f"(c_[mt][nt][0]), "+f"(c_[mt][nt][1]),
                      "+f"(c_[mt][nt][2]), "+f"(c_[mt][nt][3])
                    : "r"(a[mt][0]), "r"(a[mt][1]), "r"(a[mt][2]), "r"(a[mt][3]),
                      "r"(b0), "r"(b1));
            }
        }
    };

    // prologue
    ldgA(0, 0);
    ldB(0); ldB(1);
    stsA(0, 0);
    ldgA(0, 1);
    stsA(0, 1);
    ldgA(1, 0);
    CP_WAIT(1);
    __syncthreads();

    for (int c = 0; c < NCHUNK; c++) {
        if (c + 2 < NCHUNK) ldB(c + 2);
        if (c + 1 < NCHUNK) { stsA(c + 1, 0); ldgA(c + 1, 1); }
        mma_ks(c, 0); mma_ks(c, 1);
        if (c + 1 < NCHUNK) stsA(c + 1, 1);
        if (c + 2 < NCHUNK) ldgA(c + 2, 0);
        mma_ks(c, 2); mma_ks(c, 3);
        if (c + 2 < NCHUNK) CP_WAIT(1); else CP_WAIT(0);
        __syncthreads();
    }

    // GEMM epilogue: srow[t] = sum_c tanh(k + Vb + q) * w
#pragma unroll
    for (int mt = 0; mt < 2; mt++) {
#pragma unroll
        for (int rr = 0; rr < 2; rr++) {
            int row = warp_m * 32 + mt * 16 + rr * 8 + g;
            float partial = 0.f;
#pragma unroll
            for (int nt = 0; nt < 8; nt++) {
                int c0 = warp_n * 64 + nt * 8 + 2 * tig;
                float v0 = c_[mt][nt][2 * rr]     + sVb[c0]     + sq[c0];
                float v1 = c_[mt][nt][2 * rr + 1] + sVb[c0 + 1] + sq[c0 + 1];
                partial += tanhf(v0) * sw[c0] + tanhf(v1) * sw[c0 + 1];
            }
            partial += __shfl_xor_sync(0xffffffffu, partial, 1);
            partial += __shfl_xor_sync(0xffffffffu, partial, 2);
            if (tig == 0) atomicAdd(&srow[row], partial);
        }
    }
    __syncthreads();

    // masked-softmax partials for this 128-token tile
    bool u8 = (g_mask_u8 != 0);
    float s = -CUDART_INF_F;
    if (tid < 128) {
        size_t gidx = (size_t)b * TT + t0 + tid;
        unsigned char mk = u8 ? mask[gidx] : mask[4 * gidx];
        s = mk ? -CUDART_INF_F : (srow[tid] + wb[0]);
        float v = s;
#pragma unroll
        for (int off = 16; off; off >>= 1)
            v = fmaxf(v, __shfl_xor_sync(0xffffffffu, v, off));
        if (lane == 0) red[wid] = v;
    }
    __syncthreads();
    if (tid == 0)
        bc[0] = fmaxf(fmaxf(red[0], red[1]), fmaxf(red[2], red[3]));
    __syncthreads();
    float m_l = bc[0];

    float p = 0.f;
    if (tid < 128) {
        p = (m_l == -CUDART_INF_F) ? 0.f : __expf(s - m_l);
        srow[tid] = p;
        g_p[(size_t)b * TT + t0 + tid] = p;
        float v = p;
#pragma unroll
        for (int off = 16; off; off >>= 1)
            v += __shfl_xor_sync(0xffffffffu, v, off);
        if (lane == 0) red[wid] = v;
    }
    __syncthreads();
    if (tid == 0) {
        g_stats[b][tile][0] = m_l;
        g_stats[b][tile][1] = red[0] + red[1] + red[2] + red[3];
    }
    __syncthreads();

    // ctx partial (re-read own enc tile; mostly L2-warm)
    {
        float2 acc = make_float2(0.f, 0.f);
        const float2* ep = (const float2*)Ag + tid;
#pragma unroll 8
        for (int t = 0; t < 128; t++) {
            float2 v = ep[(size_t)t * (ENC_DIM / 2)];
            float pw = srow[t];
            acc.x += v.x * pw;
            acc.y += v.y * pw;
        }
        ((float2*)g_ctx_part)[((size_t)tile * BB + b) * (ENC_DIM / 2) + tid] = acc;
    }

    // last-CTA combine for batch b
    __threadfence();
    __syncthreads();
    if (tid == 0) s_last = (atomicAdd(&g_cnt[b], 1) == 15) ? 1 : 0;
    __syncthreads();
    if (s_last) {
        __shared__ float scale[16];
        __shared__ float bcInvS;
        if (tid == 0) {
            float m = -CUDART_INF_F;
#pragma unroll
            for (int i = 0; i < 16; i++) m = fmaxf(m, g_stats[b][i][0]);
            float S = 0.f;
#pragma unroll
            for (int i = 0; i < 16; i++) {
                float ml = g_stats[b][i][0];
                float sc = (ml == -CUDART_INF_F) ? 0.f : __expf(ml - m);
                scale[i] = sc;
                S += g_stats[b][i][1] * sc;
            }
            bcInvS = 1.f / S;
            g_cnt[b] = 0;                      // reset for next graph replay
        }
        __syncthreads();
        float invS = bcInvS;
#pragma unroll
        for (int e = tid; e < ENC_DIM; e += 256) {
            float acc = 0.f;
#pragma unroll
            for (int gi = 0; gi < 16; gi++)
                acc += g_ctx_part[gi][b][e] * scale[gi];
            out_ctx[b * ENC_DIM + e] = acc * invS;
        }
#pragma unroll
        for (int t = tid; t < TT; t += 256)
            out_w[b * TT + t] = g_p[(size_t)b * TT + t] * scale[t >> 7] * invS;
    }
}

// ---------------- launch ----------------
extern "C" void kernel_launch(void* const* d_in, const int* in_sizes, int n_in,
                              void* d_out, int out_size) {
    const float*         enc  = (const float*)d_in[0];
    const float*         dec  = (const float*)d_in[1];
    const unsigned char* mask = (const unsigned char*)d_in[2];
    const float*         Vw   = (const float*)d_in[3];
    const float*         Vb   = (const float*)d_in[4];
    const float*         Ww   = (const float*)d_in[5];
    const float*         ww   = (const float*)d_in[6];
    const float*         wb   = (const float*)d_in[7];

    float* out_ctx = (float*)d_out;                    // [B, ENC_DIM]
    float* out_w   = (float*)d_out + BB * ENC_DIM;     // [B, T]

    static int attr_done = 0;
    if (!attr_done) {
        cudaFuncSetAttribute(scores_kernel,
                             cudaFuncAttributeMaxDynamicSharedMemorySize, DYN_BYTES);
        attr_done = 1;
    }

    prep_kernel<<<BB + 64 + 32, 256>>>(dec, Ww, Vw, (const uint4*)mask);  // launch 1
    spacer_kernel<<<1, 32>>>();                                           // launch 2
    spacer_kernel<<<1, 32>>>();                                           // launch 3
    scores_kernel<<<1024, 256, DYN_BYTES>>>(enc, mask, Vb, ww, wb,
                                            out_ctx, out_w);              // launch 4 (ncu slot)
}

// round 15
// speedup vs baseline: 1.0707x; 1.0707x over previous
#include <cuda_runtime.h>
#include <cuda_fp16.h>
#include <cstdint>
#include <math_constants.h>

#define ENC_DIM 512
#define DEC_DIM 1024
#define HID     128
#define BB      64
#define TT      2048

// ---------------- scratch (no cudaMalloc allowed) ----------------
__device__ float  g_q[BB * HID];
__device__ float  g_p[BB * TT];              // unnormalized exp(s - m_local)
__device__ float  g_ctx_part[16][BB][ENC_DIM];
__device__ float  g_stats[BB][16][2];        // per-tile {m_local, sum_local}
__device__ int    g_mask_u8;                 // static-init 0; idempotent 0->1
__device__ __half g_Vw_h[HID * ENC_DIM];

// ---------------- helpers ----------------
__device__ __forceinline__ uint32_t smem_u32(const void* p) {
    uint32_t a;
    asm("{ .reg .u64 t; cvta.to.shared.u64 t, %1; cvt.u32.u64 %0, t; }" : "=r"(a) : "l"(p));
    return a;
}
__device__ __forceinline__ void cp_async16(uint32_t dst, const void* src) {
    asm volatile("cp.async.cg.shared.global [%0], [%1], 16;" :: "r"(dst), "l"(src));
}
#define CP_COMMIT()  asm volatile("cp.async.commit_group;" ::: "memory")
#define CP_WAIT(n)   asm volatile("cp.async.wait_group %0;" :: "n"(n) : "memory")

#define LDSM_X4(r0, r1, r2, r3, addr)                                        \
    asm volatile("ldmatrix.sync.aligned.m8n8.x4.shared.b16 {%0,%1,%2,%3}, [%4];" \
                 : "=r"(r0), "=r"(r1), "=r"(r2), "=r"(r3) : "r"(addr))

// ---------------- kernel 1: q projection + Vw fp16 conversion + mask detect ----
__global__ void prep_kernel(const float* __restrict__ dec,
                            const float* __restrict__ Ww,
                            const float* __restrict__ Vw,
                            const uint4* __restrict__ mask4) {
    int blk = blockIdx.x;
    int tid = threadIdx.x;     // 256
    if (blk < BB) {
        __shared__ float sdec[DEC_DIM];
        for (int i = tid; i < DEC_DIM; i += 256)
            sdec[i] = dec[blk * DEC_DIM + i];
        __syncthreads();
        if (tid < HID) {
            const float4* wr = (const float4*)(Ww + (size_t)tid * DEC_DIM);
            const float4* dr = (const float4*)sdec;
            float acc = 0.f;
#pragma unroll 8
            for (int i = 0; i < DEC_DIM / 4; i++) {
                float4 w4 = wr[i];
                float4 d4 = dr[i];
                acc += w4.x * d4.x + w4.y * d4.y + w4.z * d4.z + w4.w * d4.w;
            }
            g_q[blk * HID + tid] = acc;
        }
    } else if (blk < BB + 64) {
        int idx = (blk - BB) * 256 + tid;          // 0..16383 float4s
        float4 v = ((const float4*)Vw)[idx];
        __half2 h0 = __floats2half2_rn(v.x, v.y);
        __half2 h1 = __floats2half2_rn(v.z, v.w);
        uint2 u;
        u.x = *(unsigned*)&h0;
        u.y = *(unsigned*)&h1;
        ((uint2*)g_Vw_h)[idx] = u;
    } else {
        // mask dtype detect: 32 blocks x 256 threads = 8192 uint4 words
        int i = (blk - BB - 64) * 256 + tid;
        uint4 v = mask4[i];
        int found = (v.x > 1u) | (v.y > 1u) | (v.z > 1u) | (v.w > 1u);
        found = __any_sync(0xffffffffu, found);
        if ((tid & 31) == 0 && found) atomicOr(&g_mask_u8, 1);
    }
}

// ---------------- kernel 2: fused scores + softmax partials + ctx partial ----
// (exact R12 mainloop: KC=32, 2-stage A via LDG+F2FP+STS, 4-stage B cp.async,
//  LDSM fragments, PITCH=20)
#define KC        32
#define PITCH     20
#define TILE_W    (128 * PITCH)           // 2560 words = 10KB
#define NCHUNK    (ENC_DIM / KC)          // 16
#define A_OFF_W   0
#define B_OFF_W   (2 * TILE_W)
#define DYN_BYTES ((2 + 4) * TILE_W * 4)  // 61440 B

__global__ __launch_bounds__(256, 2) void scores_kernel(
    const float* __restrict__ enc, const unsigned char* __restrict__ mask,
    const float* __restrict__ Vb, const float* __restrict__ ww,
    const float* __restrict__ wb)
{
    extern __shared__ unsigned dsm[];
    __shared__ float sVb[HID], sq[HID], sw[HID];
    __shared__ float srow[128];
    __shared__ float red[4];
    __shared__ float bc[2];

    int bidx = blockIdx.x;         // 0..1023
    int b    = bidx >> 4;
    int tile = bidx & 15;
    int t0   = tile << 7;

    int tid    = threadIdx.x;
    int lane   = tid & 31;
    int wid    = tid >> 5;
    int warp_m = wid >> 1;         // 0..3
    int warp_n = wid & 1;          // 0..1
    int g      = lane >> 2;        // 0..7
    int tig    = lane & 3;         // 0..3

    if (tid < HID) {
        sVb[tid]  = Vb[tid];
        sq[tid]   = g_q[b * HID + tid];
        sw[tid]   = ww[tid];
        srow[tid] = 0.f;
    }

    const float*  Ag  = enc + ((size_t)(b * TT + t0)) * ENC_DIM;
    const __half* Bg  = g_Vw_h;
    uint32_t dyn_addr = smem_u32(dsm);

    // ldmatrix lane-address components
    int mat = lane >> 3;
    int ri  = lane & 7;
    uint32_t aRowByte0 = (uint32_t)(warp_m * 32 + (mat & 1) * 8 + ri) * (PITCH * 4)
                       + (uint32_t)(mat >> 1) * 16;
    uint32_t aRowByte1 = aRowByte0 + 16 * (PITCH * 4);
    uint32_t bRowByte[4];
#pragma unroll
    for (int p = 0; p < 4; p++)
        bRowByte[p] = (uint32_t)(warp_n * 64 + p * 16 + (mat >> 1) * 8 + ri) * (PITCH * 4)
                    + (uint32_t)(mat & 1) * 16;

    float4 R[4];   // A-chunk prefetch registers

    auto ldgA = [&](int c) {
        int kc = c * KC;
#pragma unroll
        for (int i = 0; i < 4; i++) {
            int idx = tid + i * 256;
            int row = idx >> 3;
            int u   = idx & 7;
            R[i] = *(const float4*)(Ag + (size_t)row * ENC_DIM + kc + u * 4);
        }
    };
    auto stsA = [&](int c) {
        unsigned* dst = dsm + A_OFF_W + (c & 1) * TILE_W;
#pragma unroll
        for (int i = 0; i < 4; i++) {
            int idx = tid + i * 256;
            int row = idx >> 3;
            int u   = idx & 7;
            __half2 h0 = __floats2half2_rn(R[i].x, R[i].y);
            __half2 h1 = __floats2half2_rn(R[i].z, R[i].w);
            uint2 v;
            v.x = *(unsigned*)&h0;
            v.y = *(unsigned*)&h1;
            *(uint2*)&dst[row * PITCH + u * 2] = v;
        }
    };
    auto ldB = [&](int c) {
        uint32_t sb = dyn_addr + (B_OFF_W + (c & 3) * TILE_W) * 4;
#pragma unroll
        for (int i = 0; i < 2; i++) {
            int idx = tid + i * 256;
            int row = idx >> 2;
            int u   = idx & 3;
            cp_async16(sb + (row * PITCH + u * 4) * 4,
                       Bg + (size_t)row * ENC_DIM + c * KC + u * 8);
        }
        CP_COMMIT();
    };

    float c_[2][8][4];
#pragma unroll
    for (int mt = 0; mt < 2; mt++)
#pragma unroll
        for (int nt = 0; nt < 8; nt++)
#pragma unroll
            for (int r = 0; r < 4; r++) c_[mt][nt][r] = 0.f;

    // prologue
    ldgA(0);
    ldB(0); ldB(1); ldB(2);
    stsA(0);
    ldgA(1);
    CP_WAIT(2);
    __syncthreads();

    for (int c = 0; c < NCHUNK; c++) {
        if (c + 1 < NCHUNK) stsA(c + 1);
        if (c + 2 < NCHUNK) ldgA(c + 2);
        if (c + 3 < NCHUNK) ldB(c + 3); else CP_COMMIT();

        uint32_t As_b = dyn_addr + (A_OFF_W + (c & 1) * TILE_W) * 4;
        uint32_t Bs_b = dyn_addr + (B_OFF_W + (c & 3) * TILE_W) * 4;

#pragma unroll
        for (int ks = 0; ks < 2; ks++) {
            uint32_t kbyte = ks * 32;
            unsigned a[2][4];
            LDSM_X4(a[0][0], a[0][1], a[0][2], a[0][3], As_b + aRowByte0 + kbyte);
            LDSM_X4(a[1][0], a[1][1], a[1][2], a[1][3], As_b + aRowByte1 + kbyte);
            unsigned bb[4][4];
#pragma unroll
            for (int p = 0; p < 4; p++)
                LDSM_X4(bb[p][0], bb[p][1], bb[p][2], bb[p][3], Bs_b + bRowByte[p] + kbyte);
#pragma unroll
            for (int nt = 0; nt < 8; nt++) {
                unsigned b0 = bb[nt >> 1][(nt & 1) * 2];
                unsigned b1 = bb[nt >> 1][(nt & 1) * 2 + 1];
#pragma unroll
                for (int mt = 0; mt < 2; mt++) {
                    asm volatile(
                        "mma.sync.aligned.m16n8k16.row.col.f32.f16.f16.f32 "
                        "{%0,%1,%2,%3}, {%4,%5,%6,%7}, {%8,%9}, {%0,%1,%2,%3};"
                        : "+f"(c_[mt][nt][0]), "+f"(c_[mt][nt][1]),
                          "+f"(c_[mt][nt][2]), "+f"(c_[mt][nt][3])
                        : "r"(a[mt][0]), "r"(a[mt][1]), "r"(a[mt][2]), "r"(a[mt][3]),
                          "r"(b0), "r"(b1));
                }
            }
        }
        CP_WAIT(2);
        __syncthreads();
    }

    // GEMM epilogue: srow[t] = sum_c tanh(k + Vb + q) * w
#pragma unroll
    for (int mt = 0; mt < 2; mt++) {
#pragma unroll
        for (int rr = 0; rr < 2; rr++) {
            int row = warp_m * 32 + mt * 16 + rr * 8 + g;
            float partial = 0.f;
#pragma unroll
            for (int nt = 0; nt < 8; nt++) {
                int c0 = warp_n * 64 + nt * 8 + 2 * tig;
                float v0 = c_[mt][nt][2 * rr]     + sVb[c0]     + sq[c0];
                float v1 = c_[mt][nt][2 * rr + 1] + sVb[c0 + 1] + sq[c0 + 1];
                partial += tanhf(v0) * sw[c0] + tanhf(v1) * sw[c0 + 1];
            }
            partial += __shfl_xor_sync(0xffffffffu, partial, 1);
            partial += __shfl_xor_sync(0xffffffffu, partial, 2);
            if (tig == 0) atomicAdd(&srow[row], partial);
        }
    }
    __syncthreads();

    // fused masked-softmax partials over this 128-token tile
    bool u8 = (g_mask_u8 != 0);
    float s = -CUDART_INF_F;
    if (tid < 128) {
        size_t gidx = (size_t)b * TT + t0 + tid;
        unsigned char mk = u8 ? mask[gidx] : mask[4 * gidx];
        s = mk ? -CUDART_INF_F : (srow[tid] + wb[0]);
        float v = s;
#pragma unroll
        for (int off = 16; off; off >>= 1)
            v = fmaxf(v, __shfl_xor_sync(0xffffffffu, v, off));
        if (lane == 0) red[wid] = v;
    }
    __syncthreads();
    if (tid == 0)
        bc[0] = fmaxf(fmaxf(red[0], red[1]), fmaxf(red[2], red[3]));
    __syncthreads();
    float m_l = bc[0];

    float p = 0.f;
    if (tid < 128) {
        p = (m_l == -CUDART_INF_F) ? 0.f : __expf(s - m_l);
        srow[tid] = p;                                // reuse as p-tile
        g_p[(size_t)b * TT + t0 + tid] = p;
        float v = p;
#pragma unroll
        for (int off = 16; off; off >>= 1)
            v += __shfl_xor_sync(0xffffffffu, v, off);
        if (lane == 0) red[wid] = v;
    }
    __syncthreads();
    if (tid == 0) {
        g_stats[b][tile][0] = m_l;
        g_stats[b][tile][1] = red[0] + red[1] + red[2] + red[3];
    }
    __syncthreads();

    // ctx partial: c_part[e] = sum_t p_t * enc[t, e]   (re-read own tile; L2-warm)
    {
        float2 acc = make_float2(0.f, 0.f);
        const float2* ep = (const float2*)Ag + tid;   // thread owns dims 2*tid, 2*tid+1
#pragma unroll 8
        for (int t = 0; t < 128; t++) {
            float2 v = ep[(size_t)t * (ENC_DIM / 2)];
            float pw = srow[t];
            acc.x += v.x * pw;
            acc.y += v.y * pw;
        }
        ((float2*)g_ctx_part)[((size_t)tile * BB + b) * (ENC_DIM / 2) + tid] = acc;
    }
}

// ---------------- kernel 3: combine (global softmax merge + outputs) ----------------
__global__ void combine_kernel(float* __restrict__ out_ctx,
                               float* __restrict__ out_w) {
    int b   = blockIdx.x;
    int tid = threadIdx.x;   // 256
    __shared__ float sm[16], ssum[16], scale[16];
    __shared__ float bcInvS;

    if (tid < 16) {
        sm[tid]   = g_stats[b][tid][0];
        ssum[tid] = g_stats[b][tid][1];
    }
    __syncthreads();
    if (tid == 0) {
        float m = -CUDART_INF_F;
#pragma unroll
        for (int i = 0; i < 16; i++) m = fmaxf(m, sm[i]);
        float S = 0.f;
#pragma unroll
        for (int i = 0; i < 16; i++) {
            float sc = (sm[i] == -CUDART_INF_F) ? 0.f : __expf(sm[i] - m);
            scale[i] = sc;
            S += ssum[i] * sc;
        }
        bcInvS = 1.f / S;
    }
    __syncthreads();
    float invS = bcInvS;

    // context: merge 16 tile partials
#pragma unroll
    for (int e = tid; e < ENC_DIM; e += 256) {
        float acc = 0.f;
#pragma unroll
        for (int gi = 0; gi < 16; gi++)
            acc += g_ctx_part[gi][b][e] * scale[gi];
        out_ctx[b * ENC_DIM + e] = acc * invS;
    }
    // weights: rescale per-tile p
#pragma unroll
    for (int t = tid; t < TT; t += 256)
        out_w[b * TT + t] = g_p[(size_t)b * TT + t] * scale[t >> 7] * invS;
}

// ---------------- launch ----------------
extern "C" void kernel_launch(void* const* d_in, const int* in_sizes, int n_in,
                              void* d_out, int out_size) {
    const float*         enc  = (const float*)d_in[0];
    const float*         dec  = (const float*)d_in[1];
    const unsigned char* mask = (const unsigned char*)d_in[2];
    const float*         Vw   = (const float*)d_in[3];
    const float*         Vb   = (const float*)d_in[4];
    const float*         Ww   = (const float*)d_in[5];
    const float*         ww   = (const float*)d_in[6];
    const float*         wb   = (const float*)d_in[7];

    float* out_ctx = (float*)d_out;                    // [B, ENC_DIM]
    float* out_w   = (float*)d_out + BB * ENC_DIM;     // [B, T]

    static int attr_done = 0;
    if (!attr_done) {
        cudaFuncSetAttribute(scores_kernel,
                             cudaFuncAttributeMaxDynamicSharedMemorySize, DYN_BYTES);
        attr_done = 1;
    }

    prep_kernel<<<BB + 64 + 32, 256>>>(dec, Ww, Vw, (const uint4*)mask);   // launch 1
    scores_kernel<<<1024, 256, DYN_BYTES>>>(enc, mask, Vb, ww, wb);        // launch 2
    combine_kernel<<<BB, 256>>>(out_ctx, out_w);                           // launch 3
}

// round 16
// speedup vs baseline: 1.1213x; 1.0472x over previous
#include <cuda_runtime.h>
#include <cuda_fp16.h>
#include <cstdint>
#include <math_constants.h>

#define ENC_DIM 512
#define DEC_DIM 1024
#define HID     128
#define BB      64
#define TT      2048

// ---------------- scratch (no cudaMalloc allowed) ----------------
__device__ float  g_q[BB * HID];
__device__ float  g_p[BB * TT];              // unnormalized exp(s - m_local)
__device__ float  g_ctx_part[16][BB][ENC_DIM];
__device__ float  g_stats[BB][16][2];        // per-tile {m_local, sum_local}
__device__ int    g_mask_u8;                 // static-init 0; idempotent 0->1
__device__ __half g_Vw_h[HID * ENC_DIM];

// ---------------- helpers ----------------
__device__ __forceinline__ uint32_t smem_u32(const void* p) {
    uint32_t a;
    asm("{ .reg .u64 t; cvta.to.shared.u64 t, %1; cvt.u32.u64 %0, t; }" : "=r"(a) : "l"(p));
    return a;
}
__device__ __forceinline__ void cp_async16(uint32_t dst, const void* src) {
    asm volatile("cp.async.cg.shared.global [%0], [%1], 16;" :: "r"(dst), "l"(src));
}
#define CP_COMMIT()  asm volatile("cp.async.commit_group;" ::: "memory")
#define CP_WAIT(n)   asm volatile("cp.async.wait_group %0;" :: "n"(n) : "memory")

#define LDSM_X4(r0, r1, r2, r3, addr)                                        \
    asm volatile("ldmatrix.sync.aligned.m8n8.x4.shared.b16 {%0,%1,%2,%3}, [%4];" \
                 : "=r"(r0), "=r"(r1), "=r"(r2), "=r"(r3) : "r"(addr))

// ---------------- kernel 1: prep (q proj + Vw fp16 convert + mask detect) ----
// 512-thread blocks. q: 4 threads per output h (quarter-K each, 64 independent
// float4 loads) -> shuffle reduce; kills the serial-chain latency of R14's prep.
__global__ __launch_bounds__(512) void prep_kernel(
    const float* __restrict__ dec, const float* __restrict__ Ww,
    const float* __restrict__ Vw, const uint4* __restrict__ mask4) {
    int blk = blockIdx.x;
    int tid = threadIdx.x;     // 512
    if (blk < BB) {
        __shared__ float sdec[DEC_DIM];
        sdec[tid]       = dec[blk * DEC_DIM + tid];
        sdec[tid + 512] = dec[blk * DEC_DIM + 512 + tid];
        __syncthreads();
        int h  = tid >> 2;                 // 0..127
        int kq = tid & 3;                  // quarter index
        const float4* wr = (const float4*)(Ww + (size_t)h * DEC_DIM) + kq * 64;
        const float4* dr = (const float4*)sdec + kq * 64;
        float acc = 0.f;
#pragma unroll 16
        for (int i = 0; i < 64; i++) {
            float4 w4 = wr[i];
            float4 d4 = dr[i];
            acc += w4.x * d4.x + w4.y * d4.y + w4.z * d4.z + w4.w * d4.w;
        }
        acc += __shfl_xor_sync(0xffffffffu, acc, 1);
        acc += __shfl_xor_sync(0xffffffffu, acc, 2);
        if (kq == 0) g_q[blk * HID + h] = acc;
    } else if (blk < BB + 32) {
        int idx = (blk - BB) * 512 + tid;          // 0..16383 float4s
        float4 v = ((const float4*)Vw)[idx];
        __half2 h0 = __floats2half2_rn(v.x, v.y);
        __half2 h1 = __floats2half2_rn(v.z, v.w);
        uint2 u;
        u.x = *(unsigned*)&h0;
        u.y = *(unsigned*)&h1;
        ((uint2*)g_Vw_h)[idx] = u;
    } else {
        // mask dtype detect: 16 blocks x 512 threads = 8192 uint4 words
        int i = (blk - BB - 32) * 512 + tid;
        uint4 v = mask4[i];
        int found = (v.x > 1u) | (v.y > 1u) | (v.z > 1u) | (v.w > 1u);
        found = __any_sync(0xffffffffu, found);
        if ((tid & 31) == 0 && found) atomicOr(&g_mask_u8, 1);
    }
}

// ---------------- kernel 2: fused scores + softmax partials + ctx partial ----
// (exact R12/R14 mainloop: KC=32, 2-stage A via LDG+F2FP+STS, 4-stage B
//  cp.async, LDSM fragments, PITCH=20)
#define KC        32
#define PITCH     20
#define TILE_W    (128 * PITCH)           // 2560 words = 10KB
#define NCHUNK    (ENC_DIM / KC)          // 16
#define A_OFF_W   0
#define B_OFF_W   (2 * TILE_W)
#define DYN_BYTES ((2 + 4) * TILE_W * 4)  // 61440 B

__global__ __launch_bounds__(256, 2) void scores_kernel(
    const float* __restrict__ enc, const unsigned char* __restrict__ mask,
    const float* __restrict__ Vb, const float* __restrict__ ww,
    const float* __restrict__ wb)
{
    extern __shared__ unsigned dsm[];
    __shared__ float sVb[HID], sq[HID], sw[HID];
    __shared__ float srow[128];
    __shared__ float red[4];
    __shared__ float bc[2];

    int bidx = blockIdx.x;         // 0..1023
    int b    = bidx >> 4;
    int tile = bidx & 15;
    int t0   = tile << 7;

    int tid    = threadIdx.x;
    int lane   = tid & 31;
    int wid    = tid >> 5;
    int warp_m = wid >> 1;         // 0..3
    int warp_n = wid & 1;          // 0..1
    int g      = lane >> 2;        // 0..7
    int tig    = lane & 3;         // 0..3

    if (tid < HID) {
        sVb[tid]  = Vb[tid];
        sq[tid]   = g_q[b * HID + tid];
        sw[tid]   = ww[tid];
        srow[tid] = 0.f;
    }

    const float*  Ag  = enc + ((size_t)(b * TT + t0)) * ENC_DIM;
    const __half* Bg  = g_Vw_h;
    uint32_t dyn_addr = smem_u32(dsm);

    // ldmatrix lane-address components
    int mat = lane >> 3;
    int ri  = lane & 7;
    uint32_t aRowByte0 = (uint32_t)(warp_m * 32 + (mat & 1) * 8 + ri) * (PITCH * 4)
                       + (uint32_t)(mat >> 1) * 16;
    uint32_t aRowByte1 = aRowByte0 + 16 * (PITCH * 4);
    uint32_t bRowByte[4];
#pragma unroll
    for (int p = 0; p < 4; p++)
        bRowByte[p] = (uint32_t)(warp_n * 64 + p * 16 + (mat >> 1) * 8 + ri) * (PITCH * 4)
                    + (uint32_t)(mat & 1) * 16;

    float4 R[4];   // A-chunk prefetch registers

    auto ldgA = [&](int c) {
        int kc = c * KC;
#pragma unroll
        for (int i = 0; i < 4; i++) {
            int idx = tid + i * 256;
            int row = idx >> 3;
            int u   = idx & 7;
            R[i] = *(const float4*)(Ag + (size_t)row * ENC_DIM + kc + u * 4);
        }
    };
    auto stsA = [&](int c) {
        unsigned* dst = dsm + A_OFF_W + (c & 1) * TILE_W;
#pragma unroll
        for (int i = 0; i < 4; i++) {
            int idx = tid + i * 256;
            int row = idx >> 3;
            int u   = idx & 7;
            __half2 h0 = __floats2half2_rn(R[i].x, R[i].y);
            __half2 h1 = __floats2half2_rn(R[i].z, R[i].w);
            uint2 v;
            v.x = *(unsigned*)&h0;
            v.y = *(unsigned*)&h1;
            *(uint2*)&dst[row * PITCH + u * 2] = v;
        }
    };
    auto ldB = [&](int c) {
        uint32_t sb = dyn_addr + (B_OFF_W + (c & 3) * TILE_W) * 4;
#pragma unroll
        for (int i = 0; i < 2; i++) {
            int idx = tid + i * 256;
            int row = idx >> 2;
            int u   = idx & 3;
            cp_async16(sb + (row * PITCH + u * 4) * 4,
                       Bg + (size_t)row * ENC_DIM + c * KC + u * 8);
        }
        CP_COMMIT();
    };

    float c_[2][8][4];
#pragma unroll
    for (int mt = 0; mt < 2; mt++)
#pragma unroll
        for (int nt = 0; nt < 8; nt++)
#pragma unroll
            for (int r = 0; r < 4; r++) c_[mt][nt][r] = 0.f;

    // prologue
    ldgA(0);
    ldB(0); ldB(1); ldB(2);
    stsA(0);
    ldgA(1);
    CP_WAIT(2);
    __syncthreads();

    for (int c = 0; c < NCHUNK; c++) {
        if (c + 1 < NCHUNK) stsA(c + 1);
        if (c + 2 < NCHUNK) ldgA(c + 2);
        if (c + 3 < NCHUNK) ldB(c + 3); else CP_COMMIT();

        uint32_t As_b = dyn_addr + (A_OFF_W + (c & 1) * TILE_W) * 4;
        uint32_t Bs_b = dyn_addr + (B_OFF_W + (c & 3) * TILE_W) * 4;

#pragma unroll
        for (int ks = 0; ks < 2; ks++) {
            uint32_t kbyte = ks * 32;
            unsigned a[2][4];
            LDSM_X4(a[0][0], a[0][1], a[0][2], a[0][3], As_b + aRowByte0 + kbyte);
            LDSM_X4(a[1][0], a[1][1], a[1][2], a[1][3], As_b + aRowByte1 + kbyte);
            unsigned bb[4][4];
#pragma unroll
            for (int p = 0; p < 4; p++)
                LDSM_X4(bb[p][0], bb[p][1], bb[p][2], bb[p][3], Bs_b + bRowByte[p] + kbyte);
#pragma unroll
            for (int nt = 0; nt < 8; nt++) {
                unsigned b0 = bb[nt >> 1][(nt & 1) * 2];
                unsigned b1 = bb[nt >> 1][(nt & 1) * 2 + 1];
#pragma unroll
                for (int mt = 0; mt < 2; mt++) {
                    asm volatile(
                        "mma.sync.aligned.m16n8k16.row.col.f32.f16.f16.f32 "
                        "{%0,%1,%2,%3}, {%4,%5,%6,%7}, {%8,%9}, {%0,%1,%2,%3};"
                        : "+f"(c_[mt][nt][0]), "+f"(c_[mt][nt][1]),
                          "+f"(c_[mt][nt][2]), "+f"(c_[mt][nt][3])
                        : "r"(a[mt][0]), "r"(a[mt][1]), "r"(a[mt][2]), "r"(a[mt][3]),
                          "r"(b0), "r"(b1));
                }
            }
        }
        CP_WAIT(2);
        __syncthreads();
    }

    // GEMM epilogue: srow[t] = sum_c tanh(k + Vb + q) * w
#pragma unroll
    for (int mt = 0; mt < 2; mt++) {
#pragma unroll
        for (int rr = 0; rr < 2; rr++) {
            int row = warp_m * 32 + mt * 16 + rr * 8 + g;
            float partial = 0.f;
#pragma unroll
            for (int nt = 0; nt < 8; nt++) {
                int c0 = warp_n * 64 + nt * 8 + 2 * tig;
                float v0 = c_[mt][nt][2 * rr]     + sVb[c0]     + sq[c0];
                float v1 = c_[mt][nt][2 * rr + 1] + sVb[c0 + 1] + sq[c0 + 1];
                partial += tanhf(v0) * sw[c0] + tanhf(v1) * sw[c0 + 1];
            }
            partial += __shfl_xor_sync(0xffffffffu, partial, 1);
            partial += __shfl_xor_sync(0xffffffffu, partial, 2);
            if (tig == 0) atomicAdd(&srow[row], partial);
        }
    }
    __syncthreads();

    // fused masked-softmax partials over this 128-token tile
    bool u8 = (g_mask_u8 != 0);
    float s = -CUDART_INF_F;
    if (tid < 128) {
        size_t gidx = (size_t)b * TT + t0 + tid;
        unsigned char mk = u8 ? mask[gidx] : mask[4 * gidx];
        s = mk ? -CUDART_INF_F : (srow[tid] + wb[0]);
        float v = s;
#pragma unroll
        for (int off = 16; off; off >>= 1)
            v = fmaxf(v, __shfl_xor_sync(0xffffffffu, v, off));
        if (lane == 0) red[wid] = v;
    }
    __syncthreads();
    if (tid == 0)
        bc[0] = fmaxf(fmaxf(red[0], red[1]), fmaxf(red[2], red[3]));
    __syncthreads();
    float m_l = bc[0];

    float p = 0.f;
    if (tid < 128) {
        p = (m_l == -CUDART_INF_F) ? 0.f : __expf(s - m_l);
        srow[tid] = p;                                // reuse as p-tile
        g_p[(size_t)b * TT + t0 + tid] = p;
        float v = p;
#pragma unroll
        for (int off = 16; off; off >>= 1)
            v += __shfl_xor_sync(0xffffffffu, v, off);
        if (lane == 0) red[wid] = v;
    }
    __syncthreads();
    if (tid == 0) {
        g_stats[b][tile][0] = m_l;
        g_stats[b][tile][1] = red[0] + red[1] + red[2] + red[3];
    }
    __syncthreads();

    // ctx partial: c_part[e] = sum_t p_t * enc[t, e]   (re-read own tile; L2-warm)
    {
        float2 acc = make_float2(0.f, 0.f);
        const float2* ep = (const float2*)Ag + tid;   // thread owns dims 2*tid, 2*tid+1
#pragma unroll 8
        for (int t = 0; t < 128; t++) {
            float2 v = ep[(size_t)t * (ENC_DIM / 2)];
            float pw = srow[t];
            acc.x += v.x * pw;
            acc.y += v.y * pw;
        }
        ((float2*)g_ctx_part)[((size_t)tile * BB + b) * (ENC_DIM / 2) + tid] = acc;
    }
}

// ---------------- kernel 3: combine (global softmax merge + outputs) ----------------
__global__ void combine_kernel(float* __restrict__ out_ctx,
                               float* __restrict__ out_w) {
    int b   = blockIdx.x;
    int tid = threadIdx.x;   // 256
    __shared__ float sm[16], ssum[16], scale[16];
    __shared__ float bcInvS;

    if (tid < 16) {
        sm[tid]   = g_stats[b][tid][0];
        ssum[tid] = g_stats[b][tid][1];
    }
    __syncthreads();
    if (tid == 0) {
        float m = -CUDART_INF_F;
#pragma unroll
        for (int i = 0; i < 16; i++) m = fmaxf(m, sm[i]);
        float S = 0.f;
#pragma unroll
        for (int i = 0; i < 16; i++) {
            float sc = (sm[i] == -CUDART_INF_F) ? 0.f : __expf(sm[i] - m);
            scale[i] = sc;
            S += ssum[i] * sc;
        }
        bcInvS = 1.f / S;
    }
    __syncthreads();
    float invS = bcInvS;

    // context: merge 16 tile partials
#pragma unroll
    for (int e = tid; e < ENC_DIM; e += 256) {
        float acc = 0.f;
#pragma unroll
        for (int gi = 0; gi < 16; gi++)
            acc += g_ctx_part[gi][b][e] * scale[gi];
        out_ctx[b * ENC_DIM + e] = acc * invS;
    }
    // weights: rescale per-tile p
#pragma unroll
    for (int t = tid; t < TT; t += 256)
        out_w[b * TT + t] = g_p[(size_t)b * TT + t] * scale[t >> 7] * invS;
}

// ---------------- launch ----------------
extern "C" void kernel_launch(void* const* d_in, const int* in_sizes, int n_in,
                              void* d_out, int out_size) {
    const float*         enc  = (const float*)d_in[0];
    const float*         dec  = (const float*)d_in[1];
    const unsigned char* mask = (const unsigned char*)d_in[2];
    const float*         Vw   = (const float*)d_in[3];
    const float*         Vb   = (const float*)d_in[4];
    const float*         Ww   = (const float*)d_in[5];
    const float*         ww   = (const float*)d_in[6];
    const float*         wb   = (const float*)d_in[7];

    float* out_ctx = (float*)d_out;                    // [B, ENC_DIM]
    float* out_w   = (float*)d_out + BB * ENC_DIM;     // [B, T]

    static int attr_done = 0;
    if (!attr_done) {
        cudaFuncSetAttribute(scores_kernel,
                             cudaFuncAttributeMaxDynamicSharedMemorySize, DYN_BYTES);
        attr_done = 1;
    }

    prep_kernel<<<BB + 32 + 16, 512>>>(dec, Ww, Vw, (const uint4*)mask);   // launch 1
    scores_kernel<<<1024, 256, DYN_BYTES>>>(enc, mask, Vb, ww, wb);        // launch 2
    combine_kernel<<<BB, 256>>>(out_ctx, out_w);                           // launch 3
}

// round 17
// speedup vs baseline: 1.2944x; 1.1544x over previous
#include <cuda_runtime.h>
#include <cuda_fp16.h>
#include <cstdint>
#include <math_constants.h>

#define ENC_DIM 512
#define DEC_DIM 1024
#define HID     128
#define BB      64
#define TT      2048

// ---------------- scratch (no cudaMalloc allowed) ----------------
__device__ float  g_q[BB * HID];
__device__ float  g_p[BB * TT];              // unnormalized exp(s - m_local)
__device__ float  g_ctx_part[16][BB][ENC_DIM];
__device__ float  g_stats[BB][16][2];        // per-tile {m_local, sum_local}
__device__ int    g_mask_u8;                 // static-init 0; idempotent 0->1
__device__ __half g_Vw_h[HID * ENC_DIM];

// ---------------- helpers ----------------
__device__ __forceinline__ uint32_t smem_u32(const void* p) {
    uint32_t a;
    asm("{ .reg .u64 t; cvta.to.shared.u64 t, %1; cvt.u32.u64 %0, t; }" : "=r"(a) : "l"(p));
    return a;
}
__device__ __forceinline__ void cp_async16(uint32_t dst, const void* src) {
    asm volatile("cp.async.cg.shared.global [%0], [%1], 16;" :: "r"(dst), "l"(src));
}
#define CP_COMMIT()  asm volatile("cp.async.commit_group;" ::: "memory")
#define CP_WAIT(n)   asm volatile("cp.async.wait_group %0;" :: "n"(n) : "memory")

#define LDSM_X4(r0, r1, r2, r3, addr)                                        \
    asm volatile("ldmatrix.sync.aligned.m8n8.x4.shared.b16 {%0,%1,%2,%3}, [%4];" \
                 : "=r"(r0), "=r"(r1), "=r"(r2), "=r"(r3) : "r"(addr))

// ---------------- kernel 1: prep (q proj + Vw fp16 convert + mask detect) ----
// q phase: warp-per-row reduction. Lanes read 32 CONSECUTIVE float4s per row
// (fully coalesced 512B warp-loads), shuffle-reduce. Kills the 8x sector
// amplification of the quarter-K layout (R15's prep was L1-traffic-bound).
__global__ __launch_bounds__(512) void prep_kernel(
    const float* __restrict__ dec, const float* __restrict__ Ww,
    const float* __restrict__ Vw, const uint4* __restrict__ mask4) {
    int blk = blockIdx.x;
    int tid = threadIdx.x;     // 512
    if (blk < BB) {
        __shared__ float sdec[DEC_DIM];
        sdec[tid]       = dec[blk * DEC_DIM + tid];
        sdec[tid + 512] = dec[blk * DEC_DIM + 512 + tid];
        __syncthreads();
        int w    = tid >> 5;               // warp 0..15
        int lane = tid & 31;
        const float4* dr = (const float4*)sdec;
#pragma unroll
        for (int j = 0; j < 8; j++) {
            int h = w * 8 + j;             // row 0..127
            const float4* wr = (const float4*)(Ww + (size_t)h * DEC_DIM);
            float acc = 0.f;
#pragma unroll
            for (int i = 0; i < 8; i++) {
                float4 w4 = wr[i * 32 + lane];
                float4 d4 = dr[i * 32 + lane];
                acc += w4.x * d4.x + w4.y * d4.y + w4.z * d4.z + w4.w * d4.w;
            }
#pragma unroll
            for (int off = 16; off; off >>= 1)
                acc += __shfl_xor_sync(0xffffffffu, acc, off);
            if (lane == 0) g_q[blk * HID + h] = acc;
        }
    } else if (blk < BB + 32) {
        int idx = (blk - BB) * 512 + tid;          // 0..16383 float4s
        float4 v = ((const float4*)Vw)[idx];
        __half2 h0 = __floats2half2_rn(v.x, v.y);
        __half2 h1 = __floats2half2_rn(v.z, v.w);
        uint2 u;
        u.x = *(unsigned*)&h0;
        u.y = *(unsigned*)&h1;
        ((uint2*)g_Vw_h)[idx] = u;
    } else {
        // mask dtype detect: 16 blocks x 512 threads = 8192 uint4 words
        int i = (blk - BB - 32) * 512 + tid;
        uint4 v = mask4[i];
        int found = (v.x > 1u) | (v.y > 1u) | (v.z > 1u) | (v.w > 1u);
        found = __any_sync(0xffffffffu, found);
        if ((tid & 31) == 0 && found) atomicOr(&g_mask_u8, 1);
    }
}

// ---------------- kernel 2: fused scores + softmax partials + ctx partial ----
// (exact R12/R14 mainloop: KC=32, 2-stage A via LDG+F2FP+STS, 4-stage B
//  cp.async, LDSM fragments, PITCH=20)
#define KC        32
#define PITCH     20
#define TILE_W    (128 * PITCH)           // 2560 words = 10KB
#define NCHUNK    (ENC_DIM / KC)          // 16
#define A_OFF_W   0
#define B_OFF_W   (2 * TILE_W)
#define DYN_BYTES ((2 + 4) * TILE_W * 4)  // 61440 B

__global__ __launch_bounds__(256, 2) void scores_kernel(
    const float* __restrict__ enc, const unsigned char* __restrict__ mask,
    const float* __restrict__ Vb, const float* __restrict__ ww,
    const float* __restrict__ wb)
{
    extern __shared__ unsigned dsm[];
    __shared__ float sVb[HID], sq[HID], sw[HID];
    __shared__ float srow[128];
    __shared__ float red[4];
    __shared__ float bc[2];

    int bidx = blockIdx.x;         // 0..1023
    int b    = bidx >> 4;
    int tile = bidx & 15;
    int t0   = tile << 7;

    int tid    = threadIdx.x;
    int lane   = tid & 31;
    int wid    = tid >> 5;
    int warp_m = wid >> 1;         // 0..3
    int warp_n = wid & 1;          // 0..1
    int g      = lane >> 2;        // 0..7
    int tig    = lane & 3;         // 0..3

    if (tid < HID) {
        sVb[tid]  = Vb[tid];
        sq[tid]   = g_q[b * HID + tid];
        sw[tid]   = ww[tid];
        srow[tid] = 0.f;
    }

    const float*  Ag  = enc + ((size_t)(b * TT + t0)) * ENC_DIM;
    const __half* Bg  = g_Vw_h;
    uint32_t dyn_addr = smem_u32(dsm);

    // ldmatrix lane-address components
    int mat = lane >> 3;
    int ri  = lane & 7;
    uint32_t aRowByte0 = (uint32_t)(warp_m * 32 + (mat & 1) * 8 + ri) * (PITCH * 4)
                       + (uint32_t)(mat >> 1) * 16;
    uint32_t aRowByte1 = aRowByte0 + 16 * (PITCH * 4);
    uint32_t bRowByte[4];
#pragma unroll
    for (int p = 0; p < 4; p++)
        bRowByte[p] = (uint32_t)(warp_n * 64 + p * 16 + (mat >> 1) * 8 + ri) * (PITCH * 4)
                    + (uint32_t)(mat & 1) * 16;

    float4 R[4];   // A-chunk prefetch registers

    auto ldgA = [&](int c) {
        int kc = c * KC;
#pragma unroll
        for (int i = 0; i < 4; i++) {
            int idx = tid + i * 256;
            int row = idx >> 3;
            int u   = idx & 7;
            R[i] = *(const float4*)(Ag + (size_t)row * ENC_DIM + kc + u * 4);
        }
    };
    auto stsA = [&](int c) {
        unsigned* dst = dsm + A_OFF_W + (c & 1) * TILE_W;
#pragma unroll
        for (int i = 0; i < 4; i++) {
            int idx = tid + i * 256;
            int row = idx >> 3;
            int u   = idx & 7;
            __half2 h0 = __floats2half2_rn(R[i].x, R[i].y);
            __half2 h1 = __floats2half2_rn(R[i].z, R[i].w);
            uint2 v;
            v.x = *(unsigned*)&h0;
            v.y = *(unsigned*)&h1;
            *(uint2*)&dst[row * PITCH + u * 2] = v;
        }
    };
    auto ldB = [&](int c) {
        uint32_t sb = dyn_addr + (B_OFF_W + (c & 3) * TILE_W) * 4;
#pragma unroll
        for (int i = 0; i < 2; i++) {
            int idx = tid + i * 256;
            int row = idx >> 2;
            int u   = idx & 3;
            cp_async16(sb + (row * PITCH + u * 4) * 4,
                       Bg + (size_t)row * ENC_DIM + c * KC + u * 8);
        }
        CP_COMMIT();
    };

    float c_[2][8][4];
#pragma unroll
    for (int mt = 0; mt < 2; mt++)
#pragma unroll
        for (int nt = 0; nt < 8; nt++)
#pragma unroll
            for (int r = 0; r < 4; r++) c_[mt][nt][r] = 0.f;

    // prologue
    ldgA(0);
    ldB(0); ldB(1); ldB(2);
    stsA(0);
    ldgA(1);
    CP_WAIT(2);
    __syncthreads();

    for (int c = 0; c < NCHUNK; c++) {
        if (c + 1 < NCHUNK) stsA(c + 1);
        if (c + 2 < NCHUNK) ldgA(c + 2);
        if (c + 3 < NCHUNK) ldB(c + 3); else CP_COMMIT();

        uint32_t As_b = dyn_addr + (A_OFF_W + (c & 1) * TILE_W) * 4;
        uint32_t Bs_b = dyn_addr + (B_OFF_W + (c & 3) * TILE_W) * 4;

#pragma unroll
        for (int ks = 0; ks < 2; ks++) {
            uint32_t kbyte = ks * 32;
            unsigned a[2][4];
            LDSM_X4(a[0][0], a[0][1], a[0][2], a[0][3], As_b + aRowByte0 + kbyte);
            LDSM_X4(a[1][0], a[1][1], a[1][2], a[1][3], As_b + aRowByte1 + kbyte);
            unsigned bb[4][4];
#pragma unroll
            for (int p = 0; p < 4; p++)
                LDSM_X4(bb[p][0], bb[p][1], bb[p][2], bb[p][3], Bs_b + bRowByte[p] + kbyte);
#pragma unroll
            for (int nt = 0; nt < 8; nt++) {
                unsigned b0 = bb[nt >> 1][(nt & 1) * 2];
                unsigned b1 = bb[nt >> 1][(nt & 1) * 2 + 1];
#pragma unroll
                for (int mt = 0; mt < 2; mt++) {
                    asm volatile(
                        "mma.sync.aligned.m16n8k16.row.col.f32.f16.f16.f32 "
                        "{%0,%1,%2,%3}, {%4,%5,%6,%7}, {%8,%9}, {%0,%1,%2,%3};"
                        : "+f"(c_[mt][nt][0]), "+f"(c_[mt][nt][1]),
                          "+f"(c_[mt][nt][2]), "+f"(c_[mt][nt][3])
                        : "r"(a[mt][0]), "r"(a[mt][1]), "r"(a[mt][2]), "r"(a[mt][3]),
                          "r"(b0), "r"(b1));
                }
            }
        }
        CP_WAIT(2);
        __syncthreads();
    }

    // GEMM epilogue: srow[t] = sum_c tanh(k + Vb + q) * w
#pragma unroll
    for (int mt = 0; mt < 2; mt++) {
#pragma unroll
        for (int rr = 0; rr < 2; rr++) {
            int row = warp_m * 32 + mt * 16 + rr * 8 + g;
            float partial = 0.f;
#pragma unroll
            for (int nt = 0; nt < 8; nt++) {
                int c0 = warp_n * 64 + nt * 8 + 2 * tig;
                float v0 = c_[mt][nt][2 * rr]     + sVb[c0]     + sq[c0];
                float v1 = c_[mt][nt][2 * rr + 1] + sVb[c0 + 1] + sq[c0 + 1];
                partial += tanhf(v0) * sw[c0] + tanhf(v1) * sw[c0 + 1];
            }
            partial += __shfl_xor_sync(0xffffffffu, partial, 1);
            partial += __shfl_xor_sync(0xffffffffu, partial, 2);
            if (tig == 0) atomicAdd(&srow[row], partial);
        }
    }
    __syncthreads();

    // fused masked-softmax partials over this 128-token tile
    bool u8 = (g_mask_u8 != 0);
    float s = -CUDART_INF_F;
    if (tid < 128) {
        size_t gidx = (size_t)b * TT + t0 + tid;
        unsigned char mk = u8 ? mask[gidx] : mask[4 * gidx];
        s = mk ? -CUDART_INF_F : (srow[tid] + wb[0]);
        float v = s;
#pragma unroll
        for (int off = 16; off; off >>= 1)
            v = fmaxf(v, __shfl_xor_sync(0xffffffffu, v, off));
        if (lane == 0) red[wid] = v;
    }
    __syncthreads();
    if (tid == 0)
        bc[0] = fmaxf(fmaxf(red[0], red[1]), fmaxf(red[2], red[3]));
    __syncthreads();
    float m_l = bc[0];

    float p = 0.f;
    if (tid < 128) {
        p = (m_l == -CUDART_INF_F) ? 0.f : __expf(s - m_l);
        srow[tid] = p;                                // reuse as p-tile
        g_p[(size_t)b * TT + t0 + tid] = p;
        float v = p;
#pragma unroll
        for (int off = 16; off; off >>= 1)
            v += __shfl_xor_sync(0xffffffffu, v, off);
        if (lane == 0) red[wid] = v;
    }
    __syncthreads();
    if (tid == 0) {
        g_stats[b][tile][0] = m_l;
        g_stats[b][tile][1] = red[0] + red[1] + red[2] + red[3];
    }
    __syncthreads();

    // ctx partial: c_part[e] = sum_t p_t * enc[t, e]   (re-read own tile; L2-warm)
    {
        float2 acc = make_float2(0.f, 0.f);
        const float2* ep = (const float2*)Ag + tid;   // thread owns dims 2*tid, 2*tid+1
#pragma unroll 8
        for (int t = 0; t < 128; t++) {
            float2 v = ep[(size_t)t * (ENC_DIM / 2)];
            float pw = srow[t];
            acc.x += v.x * pw;
            acc.y += v.y * pw;
        }
        ((float2*)g_ctx_part)[((size_t)tile * BB + b) * (ENC_DIM / 2) + tid] = acc;
    }
}

// ---------------- kernel 3: combine (global softmax merge + outputs) ----------------
__global__ void combine_kernel(float* __restrict__ out_ctx,
                               float* __restrict__ out_w) {
    int b   = blockIdx.x;
    int tid = threadIdx.x;   // 256
    __shared__ float sm[16], ssum[16], scale[16];
    __shared__ float bcInvS;

    if (tid < 16) {
        sm[tid]   = g_stats[b][tid][0];
        ssum[tid] = g_stats[b][tid][1];
    }
    __syncthreads();
    if (tid == 0) {
        float m = -CUDART_INF_F;
#pragma unroll
        for (int i = 0; i < 16; i++) m = fmaxf(m, sm[i]);
        float S = 0.f;
#pragma unroll
        for (int i = 0; i < 16; i++) {
            float sc = (sm[i] == -CUDART_INF_F) ? 0.f : __expf(sm[i] - m);
            scale[i] = sc;
            S += ssum[i] * sc;
        }
        bcInvS = 1.f / S;
    }
    __syncthreads();
    float invS = bcInvS;

    // context: merge 16 tile partials
#pragma unroll
    for (int e = tid; e < ENC_DIM; e += 256) {
        float acc = 0.f;
#pragma unroll
        for (int gi = 0; gi < 16; gi++)
            acc += g_ctx_part[gi][b][e] * scale[gi];
        out_ctx[b * ENC_DIM + e] = acc * invS;
    }
    // weights: rescale per-tile p
#pragma unroll
    for (int t = tid; t < TT; t += 256)
        out_w[b * TT + t] = g_p[(size_t)b * TT + t] * scale[t >> 7] * invS;
}

// ---------------- launch ----------------
extern "C" void kernel_launch(void* const* d_in, const int* in_sizes, int n_in,
                              void* d_out, int out_size) {
    const float*         enc  = (const float*)d_in[0];
    const float*         dec  = (const float*)d_in[1];
    const unsigned char* mask = (const unsigned char*)d_in[2];
    const float*         Vw   = (const float*)d_in[3];
    const float*         Vb   = (const float*)d_in[4];
    const float*         Ww   = (const float*)d_in[5];
    const float*         ww   = (const float*)d_in[6];
    const float*         wb   = (const float*)d_in[7];

    float* out_ctx = (float*)d_out;                    // [B, ENC_DIM]
    float* out_w   = (float*)d_out + BB * ENC_DIM;     // [B, T]

    static int attr_done = 0;
    if (!attr_done) {
        cudaFuncSetAttribute(scores_kernel,
                             cudaFuncAttributeMaxDynamicSharedMemorySize, DYN_BYTES);
        attr_done = 1;
    }

    prep_kernel<<<BB + 32 + 16, 512>>>(dec, Ww, Vw, (const uint4*)mask);   // launch 1
    scores_kernel<<<1024, 256, DYN_BYTES>>>(enc, mask, Vb, ww, wb);        // launch 2
    combine_kernel<<<BB, 256>>>(out_ctx, out_w);                           // launch 3
}